// round 4
// baseline (speedup 1.0000x reference)
#include <cuda_runtime.h>

// CrossCompress: B=16384 rows, D=128.
// item_out   = v*(e.w_vv) + e*(v.w_ev) + bias_v
// entity_out = v*(e.w_ve) + e*(v.w_ee) + bias_e
//
// R4: 8 rows/warp, MLP=16 batched LDG.128. Partial dots are accumulated as
// loads land (v/e NOT kept live through the 5-level butterfly); after the
// reduction v/e are re-loaded (L1 hits) for the combine+store. A memory
// clobber between phases prevents CSE from re-materializing 128 live regs.

#define B_ROWS 16384
#define D_DIM  128
#define RPW    8   // rows per warp

__global__ __launch_bounds__(128, 5)
void crosscompress_kernel(const float4* __restrict__ v_in,
                          const float4* __restrict__ e_in,
                          const float4* __restrict__ w_vv,
                          const float4* __restrict__ w_ve,
                          const float4* __restrict__ w_ev,
                          const float4* __restrict__ w_ee,
                          const float4* __restrict__ bias_v,
                          const float4* __restrict__ bias_e,
                          float4* __restrict__ out_item,
                          float4* __restrict__ out_ent)
{
    const int gtid = blockIdx.x * blockDim.x + threadIdx.x;
    const int warp = gtid >> 5;
    const int lane = gtid & 31;
    const int row0 = warp * RPW;               // grid sized exactly

    // Weights first (L1-resident, 512B each)
    const float4 wvv = __ldg(&w_vv[lane]);
    const float4 wev = __ldg(&w_ev[lane]);
    const float4 wve = __ldg(&w_ve[lane]);
    const float4 wee = __ldg(&w_ee[lane]);

    // Phase 1: 16 independent LDG.128; fold each into 4 dot partials
    // immediately so v/e staging regs die quickly.
    float d_vv[RPW], d_ev[RPW], d_ve[RPW], d_ee[RPW];
    #pragma unroll
    for (int r = 0; r < RPW; r++) {
        const int idx = (row0 + r) * 32 + lane;
        const float4 v4 = v_in[idx];
        const float4 e4 = e_in[idx];
        d_vv[r] = e4.x * wvv.x + e4.y * wvv.y + e4.z * wvv.z + e4.w * wvv.w;
        d_ev[r] = v4.x * wev.x + v4.y * wev.y + v4.z * wev.z + v4.w * wev.w;
        d_ve[r] = e4.x * wve.x + e4.y * wve.y + e4.z * wve.z + e4.w * wve.w;
        d_ee[r] = v4.x * wee.x + v4.y * wee.y + v4.z * wee.z + v4.w * wee.w;
    }

    // Phase 2: butterfly-reduce 32 values; 32 parallel chains per level
    #pragma unroll
    for (int off = 16; off > 0; off >>= 1) {
        #pragma unroll
        for (int r = 0; r < RPW; r++) {
            d_vv[r] += __shfl_xor_sync(0xFFFFFFFFu, d_vv[r], off);
            d_ev[r] += __shfl_xor_sync(0xFFFFFFFFu, d_ev[r], off);
            d_ve[r] += __shfl_xor_sync(0xFFFFFFFFu, d_ve[r], off);
            d_ee[r] += __shfl_xor_sync(0xFFFFFFFFu, d_ee[r], off);
        }
    }

    // Prevent CSE of the phase-3 reloads with the phase-1 loads.
    asm volatile("" ::: "memory");

    const float4 bv = __ldg(&bias_v[lane]);
    const float4 be = __ldg(&bias_e[lane]);

    // Phase 3: reload v/e (L1 hits), combine, store.
    #pragma unroll
    for (int r = 0; r < RPW; r++) {
        const int idx = (row0 + r) * 32 + lane;
        const float4 v4 = v_in[idx];
        const float4 e4 = e_in[idx];

        float4 oi, oe;
        oi.x = v4.x * d_vv[r] + e4.x * d_ev[r] + bv.x;
        oi.y = v4.y * d_vv[r] + e4.y * d_ev[r] + bv.y;
        oi.z = v4.z * d_vv[r] + e4.z * d_ev[r] + bv.z;
        oi.w = v4.w * d_vv[r] + e4.w * d_ev[r] + bv.w;

        oe.x = v4.x * d_ve[r] + e4.x * d_ee[r] + be.x;
        oe.y = v4.y * d_ve[r] + e4.y * d_ee[r] + be.y;
        oe.z = v4.z * d_ve[r] + e4.z * d_ee[r] + be.z;
        oe.w = v4.w * d_ve[r] + e4.w * d_ee[r] + be.w;

        out_item[idx] = oi;
        out_ent[idx]  = oe;
    }
}

extern "C" void kernel_launch(void* const* d_in, const int* in_sizes, int n_in,
                              void* d_out, int out_size)
{
    const float4* v_in   = (const float4*)d_in[0];
    const float4* e_in   = (const float4*)d_in[1];
    const float4* w_vv   = (const float4*)d_in[2];
    const float4* w_ve   = (const float4*)d_in[3];
    const float4* w_ev   = (const float4*)d_in[4];
    const float4* w_ee   = (const float4*)d_in[5];
    const float4* bias_v = (const float4*)d_in[6];
    const float4* bias_e = (const float4*)d_in[7];

    float* out = (float*)d_out;
    float4* out_item = (float4*)out;
    float4* out_ent  = (float4*)(out + B_ROWS * D_DIM);

    // 4 warps/block, 8 rows/warp -> 32 rows/block -> 512 blocks
    const int threads = 128;
    const int blocks  = B_ROWS / (4 * RPW);   // 512

    crosscompress_kernel<<<blocks, threads>>>(v_in, e_in, w_vv, w_ve, w_ev, w_ee,
                                              bias_v, bias_e, out_item, out_ent);
}